// round 10
// baseline (speedup 1.0000x reference)
#include <cuda_runtime.h>
#include <cuda_fp16.h>
#include <cstdint>

// Problem constants
#define G 8
#define T 4096
#define H 2048
#define E 64
#define GT (G*T)              // 32768 tokens

// Output layout (float32, concatenated in reference return order)
#define DI_OFF 0              // dispatch_indices [G,T,2,2] -> 131072
#define CW_OFF 131072         // combine_weights  [G,T,2]   -> 65536
#define AUX_OFF 196608        // scalar
#define P_OFF 196609          // router_probs [G,T,64] -> 2097152
#define Z_OFF 2293761         // scalar

// K1 tiling
#define KB 64                 // k-elems per chunk (128B fp16 rows)
#define NCH (H/KB)            // 32 chunks
#define TM 128                // tokens per CTA
#define NCTA (GT/TM)          // 256 CTAs

// K1 dynamic smem byte offsets
#define SO_BS   0                       // bias, 64 floats
#define SO_ZRED 256                     // 4 floats
#define SO_A1   1024                    // x hi limb: 2 bufs x 16KB
#define SO_A2   (SO_A1 + 32768)         // x lo limb (scaled 2^11): 2 bufs x 16KB
#define SO_B1   (SO_A2 + 32768)         // w hi limb: 2 bufs x 8KB
#define SO_B2   (SO_B1 + 16384)         // w lo limb (scaled 2^11): 2 bufs x 8KB
#define SMEM_TOTAL (SO_B2 + 16384)      // 99328 bytes
#define SO_LS   1024                    // epilogue overlay: 128 x 68 floats

#define CORR_SCALE (1.0f/2048.0f)

// K2 dynamic smem layout (bytes)
#define K2_SKEY 0                       // uint32 skey[4096]
#define K2_BASE 16384                   // int base[4097]
#define K2_CNT  32784                   // int cnt[4096]
#define K2_BTOK 49168                   // short btok[4096]
#define K2_SMEM (K2_BTOK + 8192)        // 57360 bytes

// -------- scratch (device globals; no allocation allowed) --------
__device__ float g_gate0[GT];
__device__ float g_gate1[GT];
__device__ int   g_e0[GT];
__device__ int   g_e1[GT];
__device__ int   g_sorted[GT];   // packed: tok | e0<<12 | e1<<18 (rank order)
__device__ int   g_prio0[GT];
__device__ int   g_prio1[GT];
__device__ float g_zpart[NCTA];
__device__ int   g_cnt[G*E];
__device__ float g_psum2[NCTA*E];   // per-CTA prob sums (deterministic)
__device__ __half g_w1[E*H];   // W^T hi limb [expert][k]
__device__ __half g_w2[E*H];   // W^T lo limb, scaled by 2^11

__device__ __forceinline__ uint32_t smem_u32(const void* p) {
    uint32_t a;
    asm("{ .reg .u64 t; cvta.to.shared.u64 t, %1; cvt.u32.u64 %0, t; }"
        : "=r"(a) : "l"(p));
    return a;
}
__device__ __forceinline__ void ldsm4(uint32_t* r, uint32_t a) {
    asm volatile("ldmatrix.sync.aligned.m8n8.x4.shared.b16 {%0,%1,%2,%3}, [%4];"
        : "=r"(r[0]), "=r"(r[1]), "=r"(r[2]), "=r"(r[3]) : "r"(a));
}
__device__ __forceinline__ void mma16816(float* c, const uint32_t* a, const uint32_t* b) {
    asm volatile("mma.sync.aligned.m16n8k16.row.col.f32.f16.f16.f32 "
        "{%0,%1,%2,%3}, {%4,%5,%6,%7}, {%8,%9}, {%0,%1,%2,%3};"
        : "+f"(c[0]), "+f"(c[1]), "+f"(c[2]), "+f"(c[3])
        : "r"(a[0]), "r"(a[1]), "r"(a[2]), "r"(a[3]), "r"(b[0]), "r"(b[1]));
}
__device__ __forceinline__ void mma16816h(uint32_t* c, const uint32_t* a, const uint32_t* b) {
    asm volatile("mma.sync.aligned.m16n8k16.row.col.f16.f16.f16.f16 "
        "{%0,%1}, {%2,%3,%4,%5}, {%6,%7}, {%0,%1};"
        : "+r"(c[0]), "+r"(c[1])
        : "r"(a[0]), "r"(a[1]), "r"(a[2]), "r"(a[3]), "r"(b[0]), "r"(b[1]));
}
__device__ __forceinline__ uint32_t h2u(__half2 h) {
    return *reinterpret_cast<uint32_t*>(&h);
}

// ---------------- K0: zero counters + preconvert W^T into fp16 limbs ----------------
__global__ __launch_bounds__(256) void k0_prep(const float* __restrict__ W) {
    int gidx = blockIdx.x * 256 + threadIdx.x;     // 128 CTAs -> 32768 threads
    if (gidx < G*E) g_cnt[gidx] = 0;
    // H*16 float4 granules: k = gidx>>4, experts 4q..4q+3
    int k = gidx >> 4, q = gidx & 15;
    float4 v = reinterpret_cast<const float4*>(W)[gidx];
    float xs[4] = {v.x, v.y, v.z, v.w};
#pragma unroll
    for (int j = 0; j < 4; ++j) {
        int e = 4*q + j;
        __half hi = __float2half_rn(xs[j]);
        float hf = __half2float(hi);
        __half lo = __float2half_rn((xs[j] - hf) * 2048.0f);  // pre-scaled limb
        g_w1[e*H + k] = hi;
        g_w2[e*H + k] = lo;
    }
}

// ---------------- K1: mma.sync GEMM (2-limb fp16, f16-accum corrections) ----------------
// 256 threads (8 warps: 4 M x 2 N), 128 tokens/CTA, chunks of K=64.
// Main pass x1*w1 in fp32 accum; corrections x1*w2' + x2'*w1 (both scaled 2^11)
// in ONE fp16 accumulator at 2x MMA rate; epilogue adds corr * 2^-11.
__global__ __launch_bounds__(256, 2) void k1_gemm(
    const float* __restrict__ X, const float* __restrict__ Bv,
    float* __restrict__ out)
{
    extern __shared__ __align__(16) char smem[];
    __shared__ float psums[4][64];
    const uint32_t sb = smem_u32(smem);
    const int tid = threadIdx.x;
    const int wid = tid >> 5, lane = tid & 31;
    const int wm = wid >> 1, wn = wid & 1;
    const int tok0 = blockIdx.x * TM;

    if (tid < 64) *reinterpret_cast<float*>(smem + SO_BS + tid*4) = Bv[tid];

    float acc[2][4][4];
    uint32_t acch[2][4][2];
#pragma unroll
    for (int mt = 0; mt < 2; ++mt)
#pragma unroll
        for (int nt = 0; nt < 4; ++nt) {
#pragma unroll
            for (int i = 0; i < 4; ++i) acc[mt][nt][i] = 0.f;
            acch[mt][nt][0] = 0u; acch[mt][nt][1] = 0u;
        }

    float4 xv[8];

    auto ldg_chunk = [&](int ch) {
        const int hc = ch * KB;
#pragma unroll
        for (int it = 0; it < 8; ++it) {
            int idx = it*256 + tid, row = idx >> 4, q = idx & 15;
            xv[it] = *reinterpret_cast<const float4*>(
                X + (size_t)(tok0 + row)*H + hc + q*4);
        }
    };

    auto sts_chunk = [&](int ch, int buf) {
        const int hc = ch * KB;
        char* A1 = smem + SO_A1 + buf*16384;
        char* A2 = smem + SO_A2 + buf*16384;
#pragma unroll
        for (int it = 0; it < 8; ++it) {
            int idx = it*256 + tid, row = idx >> 4, q = idx & 15;
            float4 v = xv[it];
            __half2 h01 = __floats2half2_rn(v.x, v.y);
            __half2 h23 = __floats2half2_rn(v.z, v.w);
            float2 f01 = __half22float2(h01);
            float2 f23 = __half22float2(h23);
            __half2 l01 = __floats2half2_rn((v.x - f01.x)*2048.f, (v.y - f01.y)*2048.f);
            __half2 l23 = __floats2half2_rn((v.z - f23.x)*2048.f, (v.w - f23.y)*2048.f);
            int offs = row*128 + ((((q >> 1) ^ (row & 7)) << 4) | ((q & 1) << 3));
            *reinterpret_cast<uint2*>(A1 + offs) = make_uint2(h2u(h01), h2u(h23));
            *reinterpret_cast<uint2*>(A2 + offs) = make_uint2(h2u(l01), h2u(l23));
        }
        // W loaded inline (L2-resident; no long-lived staging regs)
        char* B1 = smem + SO_B1 + buf*8192;
        char* B2 = smem + SO_B2 + buf*8192;
#pragma unroll
        for (int it = 0; it < 2; ++it) {
            int idx = it*256 + tid, e = idx >> 3, g = idx & 7;
            uint4 w1v = reinterpret_cast<const uint4*>(g_w1 + (size_t)e*H + hc)[g];
            uint4 w2v = reinterpret_cast<const uint4*>(g_w2 + (size_t)e*H + hc)[g];
            int offs = e*128 + ((g ^ (e & 7)) << 4);
            *reinterpret_cast<uint4*>(B1 + offs) = w1v;
            *reinterpret_cast<uint4*>(B2 + offs) = w2v;
        }
    };

    auto comp_chunk = [&](int buf) {
        const uint32_t sA1 = sb + SO_A1 + buf*16384;
        const uint32_t sB1 = sb + SO_B1 + buf*8192;
#pragma unroll
        for (int ks = 0; ks < 4; ++ks) {
            const int kb = ks*2;
            uint32_t a1f[2][4], a2f[2][4], b1f[2][4], b2f[2][4];
#pragma unroll
            for (int mt = 0; mt < 2; ++mt) {
                int row = wm*32 + mt*16 + (lane & 15);
                int col = (kb + (lane >> 4)) ^ (row & 7);
                uint32_t ad = sA1 + row*128 + col*16;
                ldsm4(a1f[mt], ad);
                ldsm4(a2f[mt], ad + (SO_A2 - SO_A1));
            }
#pragma unroll
            for (int ng = 0; ng < 2; ++ng) {
                int rowb = wn*32 + ng*16 + (lane & 7) + ((lane >> 4) << 3);
                int colb = (kb + ((lane >> 3) & 1)) ^ (rowb & 7);
                uint32_t bd = sB1 + rowb*128 + colb*16;
                ldsm4(b1f[ng], bd);
                ldsm4(b2f[ng], bd + (SO_B2 - SO_B1));
            }
#pragma unroll
            for (int mt = 0; mt < 2; ++mt)
#pragma unroll
                for (int ng = 0; ng < 2; ++ng)
#pragma unroll
                    for (int hf = 0; hf < 2; ++hf) {
                        float* c = acc[mt][ng*2 + hf];
                        uint32_t* ch = acch[mt][ng*2 + hf];
                        mma16816(c, a1f[mt], &b1f[ng][hf*2]);
                        mma16816h(ch, a1f[mt], &b2f[ng][hf*2]);
                        mma16816h(ch, a2f[mt], &b1f[ng][hf*2]);
                    }
        }
    };

    ldg_chunk(0);
    sts_chunk(0, 0);
#pragma unroll 1
    for (int ch = 0; ch < NCH; ++ch) {
        if (ch + 1 < NCH) ldg_chunk(ch + 1);
        __syncthreads();
        comp_chunk(ch & 1);
        if (ch + 1 < NCH) sts_chunk(ch + 1, (ch + 1) & 1);
    }
    __syncthreads();   // all comp done; safe to overlay ls

    // ---- dump accumulators (+ scaled corrections) to ls[128][68] ----
    float* ls = reinterpret_cast<float*>(smem + SO_LS);
#pragma unroll
    for (int mt = 0; mt < 2; ++mt)
#pragma unroll
        for (int nt = 0; nt < 4; ++nt) {
            int row = wm*32 + mt*16 + (lane >> 2);
            int col = wn*32 + nt*8 + (lane & 3)*2;
            __half2 hc0 = *reinterpret_cast<__half2*>(&acch[mt][nt][0]);
            __half2 hc1 = *reinterpret_cast<__half2*>(&acch[mt][nt][1]);
            float2 c01 = __half22float2(hc0);
            float2 c23 = __half22float2(hc1);
            *reinterpret_cast<float2*>(ls + row*68 + col) =
                make_float2(acc[mt][nt][0] + c01.x*CORR_SCALE,
                            acc[mt][nt][1] + c01.y*CORR_SCALE);
            *reinterpret_cast<float2*>(ls + (row + 8)*68 + col) =
                make_float2(acc[mt][nt][2] + c23.x*CORR_SCALE,
                            acc[mt][nt][3] + c23.y*CORR_SCALE);
        }
    __syncthreads();

    // ---- per-token epilogue (warps 0-3, 1 token per thread) ----
    float* bs = reinterpret_cast<float*>(smem + SO_BS);
    float* zred = reinterpret_cast<float*>(smem + SO_ZRED);
    float lg[64];
    float zl = 0.f;
    if (tid < 128) {
        const int t = tid;
#pragma unroll
        for (int e = 0; e < 64; ++e) lg[e] = ls[t*68 + e] + bs[e];

        float mx = lg[0];
#pragma unroll
        for (int e = 1; e < 64; ++e) mx = fmaxf(mx, lg[e]);
        float ssum = 0.f;
#pragma unroll
        for (int e = 0; e < 64; ++e) { float p = expf(lg[e] - mx); lg[e] = p; ssum += p; }
        float logz = mx + logf(ssum);
        float inv = 1.f / ssum;
#pragma unroll
        for (int e = 0; e < 64; ++e) lg[e] *= inv;

        float p0 = -1.f, p1 = -1.f; int i0 = 0, i1 = 0;
#pragma unroll
        for (int e = 0; e < 64; ++e) {
            float v = lg[e];
            if (v > p0) { p1 = p0; i1 = i0; p0 = v; i0 = e; }
            else if (v > p1) { p1 = v; i1 = e; }
        }
        const int token = tok0 + t;
        g_gate0[token] = p0; g_gate1[token] = p1;
        g_e0[token] = i0;    g_e1[token] = i1;
        const int grp = token >> 12;
        atomicAdd(&g_cnt[grp*E + i0], 1);
        atomicAdd(&g_cnt[grp*E + i1], 1);
        zl = logz * logz;
    }
    __syncthreads();

    if (tid < 128) {
        // probs back into ls
        float* row = ls + tid*68;
#pragma unroll
        for (int c = 0; c < 16; ++c)
            *reinterpret_cast<float4*>(row + c*4) =
                make_float4(lg[4*c], lg[4*c+1], lg[4*c+2], lg[4*c+3]);
#pragma unroll
        for (int o = 16; o; o >>= 1) zl += __shfl_xor_sync(0xffffffffu, zl, o);
        if (lane == 0) zred[wid] = zl;
    }
    __syncthreads();

    // coalesced prob copy-out + deterministic per-CTA per-expert sums
    // (expert id k&63 is invariant under stride 256)
    float* P = out + P_OFF + (size_t)tok0*64;
    float s = 0.f;
    for (int k = tid; k < TM*64; k += 256) {
        float v = ls[(k >> 6)*68 + (k & 63)];
        P[k] = v;
        s += v;
    }
    psums[tid >> 6][tid & 63] = s;
    __syncthreads();
    if (tid < 64)
        g_psum2[blockIdx.x*64 + tid] =
            psums[0][tid] + psums[1][tid] + psums[2][tid] + psums[3][tid];

    if (tid == 0)
        g_zpart[blockIdx.x] = zred[0] + zred[1] + zred[2] + zred[3];
}

// ---------------- K2: bucket-based stable rank by gate0 (descending) ----------------
// One CTA per group, 1024 threads. key = ~fbits(gate0) (ascending uint ==
// descending float, exact). 12-bit high-bucket histogram + block scan +
// counting scatter; each token ranks only within its own bucket.
__global__ __launch_bounds__(1024) void k2_rank() {
    extern __shared__ __align__(16) char k2s[];
    uint32_t* skey = reinterpret_cast<uint32_t*>(k2s + K2_SKEY);  // [4096]
    int*      base = reinterpret_cast<int*>(k2s + K2_BASE);       // [4097]
    int*      cnt  = reinterpret_cast<int*>(k2s + K2_CNT);        // [4096]
    short*    btok = reinterpret_cast<short*>(k2s + K2_BTOK);     // [4096]
    __shared__ int wsum[32];

    const int tid = threadIdx.x;
    const int grp = blockIdx.x;
    const int wid = tid >> 5, lane = tid & 31;

    // load keys, zero hist + cnt
    for (int t = tid; t < T; t += 1024) {
        skey[t] = ~__float_as_uint(g_gate0[grp*T + t]);
        base[t] = 0;
        cnt[t] = 0;
    }
    if (tid == 0) base[T] = 0;
    __syncthreads();

    // histogram on high 12 bits
    for (int t = tid; t < T; t += 1024)
        atomicAdd(&base[skey[t] >> 20], 1);
    __syncthreads();

    // block exclusive scan of base[0..4095] (4 buckets per thread)
    const int i0 = tid * 4;
    int b0 = base[i0], b1 = base[i0+1], b2 = base[i0+2], b3 = base[i0+3];
    int local = b0 + b1 + b2 + b3;
    int incl = local;
#pragma unroll
    for (int o = 1; o < 32; o <<= 1) {
        int n = __shfl_up_sync(0xffffffffu, incl, o);
        if (lane >= o) incl += n;
    }
    if (lane == 31) wsum[wid] = incl;
    __syncthreads();
    if (tid < 32) {
        int v = wsum[tid];
        int sc = v;
#pragma unroll
        for (int o = 1; o < 32; o <<= 1) {
            int n = __shfl_up_sync(0xffffffffu, sc, o);
            if (tid >= o) sc += n;
        }
        wsum[tid] = sc - v;     // exclusive warp base
    }
    __syncthreads();
    {
        int pref = wsum[wid] + incl - local;
        base[i0]   = pref;
        base[i0+1] = pref + b0;
        base[i0+2] = pref + b0 + b1;
        base[i0+3] = pref + b0 + b1 + b2;
        if (tid == 1023) base[T] = pref + local;   // == T
    }
    __syncthreads();

    // counting scatter into bucket-grouped order
    for (int t = tid; t < T; t += 1024) {
        int b = skey[t] >> 20;
        int off = atomicAdd(&cnt[b], 1);
        btok[base[b] + off] = (short)t;
    }
    __syncthreads();

    // rank within bucket; cross-bucket handled by base prefix
    for (int t = tid; t < T; t += 1024) {
        uint32_t kt = skey[t];
        int b = kt >> 20;
        int s0 = base[b], s1 = base[b+1];
        int r = s0;
        for (int s = s0; s < s1; ++s) {
            int j = btok[s];
            uint32_t kj = skey[j];
            r += (kj < kt) || (kj == kt && j < t);
        }
        int e0 = g_e0[grp*T + t], e1 = g_e1[grp*T + t];
        g_sorted[grp*T + r] = t | (e0 << 12) | (e1 << 18);
    }
}

// ---------------- K3a: expert buffer priorities ----------------
// 1024 threads; sequential packed load, 32 warp segments, warp-local running
// counts, exclusive scan over warp histograms, scatter priorities.
__global__ __launch_bounds__(1024) void k3a_prio() {
    __shared__ unsigned char se[2*T];
    __shared__ unsigned char soff[2*T];
    __shared__ short stok[T];
    __shared__ int wcnt[32][64];
    __shared__ int wbase[32][64];

    const int tid = threadIdx.x;
    const int grp = blockIdx.x;
    const int w = tid >> 5, lane = tid & 31;
    const unsigned lt = (1u << lane) - 1u;

    wcnt[w][lane] = 0;
    wcnt[w][lane + 32] = 0;

    // sequential packed load: one coalesced pass fills tok, e0, e1
    for (int p = tid; p < T; p += 1024) {
        int pk = g_sorted[grp*T + p];
        stok[p] = (short)(pk & 4095);
        se[p]     = (unsigned char)((pk >> 12) & 63);
        se[p + T] = (unsigned char)((pk >> 18) & 63);
    }
    __syncthreads();

    // warp-sequential running counts over 8 sub-chunks of each 256-segment
#pragma unroll
    for (int i = 0; i < 8; ++i) {
        int p = w*256 + i*32 + lane;
        int e = se[p];
        unsigned m = __match_any_sync(0xffffffffu, e);
        int lrank = __popc(m & lt);
        int off = wcnt[w][e] + lrank;
        soff[p] = (unsigned char)off;
        __syncwarp();
        if (lane == (__ffs(m) - 1)) wcnt[w][e] += __popc(m);
        __syncwarp();
    }
    __syncthreads();

    // exclusive scan over warps, per expert
    if (tid < 64) {
        int run = 0;
#pragma unroll
        for (int ww = 0; ww < 32; ++ww) {
            wbase[ww][tid] = run;
            run += wcnt[ww][tid];
        }
    }
    __syncthreads();

    // scatter priorities back to token order
#pragma unroll
    for (int i = 0; i < 8; ++i) {
        int p = i*1024 + tid;
        int prio = wbase[p >> 8][se[p]] + soff[p];
        int tok = stok[p & (T-1)];
        if (p < T) g_prio0[grp*T + tok] = prio; else g_prio1[grp*T + tok] = prio;
    }
}

// ---------------- K3b: dispatch/combine outputs (fully parallel) ----------------
__global__ __launch_bounds__(256) void k3b_out(float* __restrict__ out,
                                               const int* __restrict__ capPtr) {
    const int idx = blockIdx.x * 256 + threadIdx.x;   // one token per thread
    const int cap = capPtr ? *capPtr : 160;
    int e0 = g_e0[idx], e1 = g_e1[idx];
    int pr0 = g_prio0[idx], pr1 = g_prio1[idx];
    float gt0 = g_gate0[idx], gt1 = g_gate1[idx];
    float4 d = make_float4((float)e0, (float)pr0, (float)e1, (float)pr1);
    reinterpret_cast<float4*>(out + DI_OFF)[idx] = d;
    float2 cc = make_float2(pr0 < cap ? gt0 : 0.f, pr1 < cap ? gt1 : 0.f);
    reinterpret_cast<float2*>(out + CW_OFF)[idx] = cc;
}

// ---------------- K5: final scalars (deterministic reduction of per-CTA sums) ----------------
__global__ __launch_bounds__(512) void k5_final(float* __restrict__ out) {
    __shared__ float red[16];
    const int tid = threadIdx.x;       // 512 = 8 groups x 64 experts
    const int g = tid >> 6, e = tid & 63;
    float ps = 0.f;
#pragma unroll
    for (int c = 0; c < 32; ++c) ps += g_psum2[(g*32 + c)*64 + e];
    float a = (float)g_cnt[g*E + e] * ps;
#pragma unroll
    for (int o = 16; o; o >>= 1) a += __shfl_xor_sync(0xffffffffu, a, o);
    if ((tid & 31) == 0) red[tid >> 5] = a;
    __syncthreads();
    if (tid == 0) {
        float s = 0.f;
#pragma unroll
        for (int i = 0; i < 16; ++i) s += red[i];
        float z = 0.f;
        for (int i = 0; i < NCTA; ++i) z += g_zpart[i];
        out[AUX_OFF] = s * (1.f / 2097152.f);
        out[Z_OFF]   = z * (1.f / 32768.f);
    }
}

extern "C" void kernel_launch(void* const* d_in, const int* in_sizes, int n_in,
                              void* d_out, int out_size) {
    const float* X = (const float*)d_in[0];
    const float* W = (const float*)d_in[1];
    const float* B = (const float*)d_in[2];
    const int* cap = (n_in > 3) ? (const int*)d_in[3] : nullptr;
    float* out = (float*)d_out;

    cudaFuncSetAttribute(k1_gemm, cudaFuncAttributeMaxDynamicSharedMemorySize, SMEM_TOTAL);
    cudaFuncSetAttribute(k2_rank, cudaFuncAttributeMaxDynamicSharedMemorySize, K2_SMEM);

    k0_prep<<<128, 256>>>(W);
    k1_gemm<<<NCTA, 256, SMEM_TOTAL>>>(X, B, out);
    k2_rank<<<G, 1024, K2_SMEM>>>();
    k3a_prio<<<G, 1024>>>();
    k3b_out<<<GT/256, 256>>>(out, cap);
    k5_final<<<1, 512>>>(out);
}

// round 11
// speedup vs baseline: 1.4557x; 1.4557x over previous
#include <cuda_runtime.h>
#include <cuda_fp16.h>
#include <cstdint>

// Problem constants
#define G 8
#define T 4096
#define H 2048
#define E 64
#define GT (G*T)              // 32768 tokens

// Output layout (float32, concatenated in reference return order)
#define DI_OFF 0              // dispatch_indices [G,T,2,2] -> 131072
#define CW_OFF 131072         // combine_weights  [G,T,2]   -> 65536
#define AUX_OFF 196608        // scalar
#define P_OFF 196609          // router_probs [G,T,64] -> 2097152
#define Z_OFF 2293761         // scalar

// K1 tiling
#define KB 64                 // k-elems per chunk (128B fp16 rows)
#define NCH (H/KB)            // 32 chunks
#define TM 128                // tokens per CTA
#define NCTA (GT/TM)          // 256 CTAs

// K1 dynamic smem byte offsets
#define SO_BS   0                       // bias, 64 floats
#define SO_ZRED 256                     // 4 floats
#define SO_A1   1024                    // x hi limb: 2 bufs x 16KB
#define SO_A2   (SO_A1 + 32768)         // x lo limb (scaled 2^11): 2 bufs x 16KB
#define SO_B1   (SO_A2 + 32768)         // w hi limb: 2 bufs x 8KB
#define SO_B2   (SO_B1 + 16384)         // w lo limb (scaled 2^11): 2 bufs x 8KB
#define SMEM_TOTAL (SO_B2 + 16384)      // 99328 bytes
#define SO_LS   1024                    // epilogue overlay: 128 x 68 floats

#define CORR_SCALE (1.0f/2048.0f)

// -------- scratch (device globals; no allocation allowed) --------
__device__ float g_gate0[GT];
__device__ float g_gate1[GT];
__device__ int   g_e0[GT];
__device__ int   g_e1[GT];
__device__ int   g_sorted[GT];   // packed: tok | e0<<12 | e1<<18 (rank order)
__device__ int   g_prio0[GT];
__device__ int   g_prio1[GT];
__device__ float g_zpart[NCTA];
__device__ int   g_cnt[G*E];
__device__ float g_psum2[NCTA*E];   // per-CTA prob sums (deterministic)
__device__ __half g_w1[E*H];   // W^T hi limb [expert][k]
__device__ __half g_w2[E*H];   // W^T lo limb, scaled by 2^11

__device__ __forceinline__ uint32_t smem_u32(const void* p) {
    uint32_t a;
    asm("{ .reg .u64 t; cvta.to.shared.u64 t, %1; cvt.u32.u64 %0, t; }"
        : "=r"(a) : "l"(p));
    return a;
}
__device__ __forceinline__ void ldsm4(uint32_t* r, uint32_t a) {
    asm volatile("ldmatrix.sync.aligned.m8n8.x4.shared.b16 {%0,%1,%2,%3}, [%4];"
        : "=r"(r[0]), "=r"(r[1]), "=r"(r[2]), "=r"(r[3]) : "r"(a));
}
__device__ __forceinline__ void mma16816(float* c, const uint32_t* a, const uint32_t* b) {
    asm volatile("mma.sync.aligned.m16n8k16.row.col.f32.f16.f16.f32 "
        "{%0,%1,%2,%3}, {%4,%5,%6,%7}, {%8,%9}, {%0,%1,%2,%3};"
        : "+f"(c[0]), "+f"(c[1]), "+f"(c[2]), "+f"(c[3])
        : "r"(a[0]), "r"(a[1]), "r"(a[2]), "r"(a[3]), "r"(b[0]), "r"(b[1]));
}
__device__ __forceinline__ void mma16816h(uint32_t* c, const uint32_t* a, const uint32_t* b) {
    asm volatile("mma.sync.aligned.m16n8k16.row.col.f16.f16.f16.f16 "
        "{%0,%1}, {%2,%3,%4,%5}, {%6,%7}, {%0,%1};"
        : "+r"(c[0]), "+r"(c[1])
        : "r"(a[0]), "r"(a[1]), "r"(a[2]), "r"(a[3]), "r"(b[0]), "r"(b[1]));
}
__device__ __forceinline__ uint32_t h2u(__half2 h) {
    return *reinterpret_cast<uint32_t*>(&h);
}

// ---------------- K0: zero counters + preconvert W^T into fp16 limbs ----------------
__global__ __launch_bounds__(256) void k0_prep(const float* __restrict__ W) {
    int gidx = blockIdx.x * 256 + threadIdx.x;     // 128 CTAs -> 32768 threads
    if (gidx < G*E) g_cnt[gidx] = 0;
    // H*16 float4 granules: k = gidx>>4, experts 4q..4q+3
    int k = gidx >> 4, q = gidx & 15;
    float4 v = reinterpret_cast<const float4*>(W)[gidx];
    float xs[4] = {v.x, v.y, v.z, v.w};
#pragma unroll
    for (int j = 0; j < 4; ++j) {
        int e = 4*q + j;
        __half hi = __float2half_rn(xs[j]);
        float hf = __half2float(hi);
        __half lo = __float2half_rn((xs[j] - hf) * 2048.0f);  // pre-scaled limb
        g_w1[e*H + k] = hi;
        g_w2[e*H + k] = lo;
    }
}

// ---------------- K1: mma.sync GEMM (2-limb fp16, f16-accum corrections) ----------------
// 256 threads (8 warps: 4 M x 2 N), 128 tokens/CTA, chunks of K=64.
// Main pass x1*w1 in fp32 accum; corrections x1*w2' + x2'*w1 (both scaled 2^11)
// in ONE fp16 accumulator at 2x MMA rate; epilogue adds corr * 2^-11.
__global__ __launch_bounds__(256, 2) void k1_gemm(
    const float* __restrict__ X, const float* __restrict__ Bv,
    float* __restrict__ out)
{
    extern __shared__ __align__(16) char smem[];
    __shared__ float psums[4][64];
    const uint32_t sb = smem_u32(smem);
    const int tid = threadIdx.x;
    const int wid = tid >> 5, lane = tid & 31;
    const int wm = wid >> 1, wn = wid & 1;
    const int tok0 = blockIdx.x * TM;

    if (tid < 64) *reinterpret_cast<float*>(smem + SO_BS + tid*4) = Bv[tid];

    float acc[2][4][4];
    uint32_t acch[2][4][2];
#pragma unroll
    for (int mt = 0; mt < 2; ++mt)
#pragma unroll
        for (int nt = 0; nt < 4; ++nt) {
#pragma unroll
            for (int i = 0; i < 4; ++i) acc[mt][nt][i] = 0.f;
            acch[mt][nt][0] = 0u; acch[mt][nt][1] = 0u;
        }

    float4 xv[8];

    auto ldg_chunk = [&](int ch) {
        const int hc = ch * KB;
#pragma unroll
        for (int it = 0; it < 8; ++it) {
            int idx = it*256 + tid, row = idx >> 4, q = idx & 15;
            xv[it] = *reinterpret_cast<const float4*>(
                X + (size_t)(tok0 + row)*H + hc + q*4);
        }
    };

    auto sts_chunk = [&](int ch, int buf) {
        const int hc = ch * KB;
        char* A1 = smem + SO_A1 + buf*16384;
        char* A2 = smem + SO_A2 + buf*16384;
#pragma unroll
        for (int it = 0; it < 8; ++it) {
            int idx = it*256 + tid, row = idx >> 4, q = idx & 15;
            float4 v = xv[it];
            __half2 h01 = __floats2half2_rn(v.x, v.y);
            __half2 h23 = __floats2half2_rn(v.z, v.w);
            float2 f01 = __half22float2(h01);
            float2 f23 = __half22float2(h23);
            __half2 l01 = __floats2half2_rn((v.x - f01.x)*2048.f, (v.y - f01.y)*2048.f);
            __half2 l23 = __floats2half2_rn((v.z - f23.x)*2048.f, (v.w - f23.y)*2048.f);
            int offs = row*128 + ((((q >> 1) ^ (row & 7)) << 4) | ((q & 1) << 3));
            *reinterpret_cast<uint2*>(A1 + offs) = make_uint2(h2u(h01), h2u(h23));
            *reinterpret_cast<uint2*>(A2 + offs) = make_uint2(h2u(l01), h2u(l23));
        }
        // W loaded inline (L2-resident; no long-lived staging regs)
        char* B1 = smem + SO_B1 + buf*8192;
        char* B2 = smem + SO_B2 + buf*8192;
#pragma unroll
        for (int it = 0; it < 2; ++it) {
            int idx = it*256 + tid, e = idx >> 3, g = idx & 7;
            uint4 w1v = reinterpret_cast<const uint4*>(g_w1 + (size_t)e*H + hc)[g];
            uint4 w2v = reinterpret_cast<const uint4*>(g_w2 + (size_t)e*H + hc)[g];
            int offs = e*128 + ((g ^ (e & 7)) << 4);
            *reinterpret_cast<uint4*>(B1 + offs) = w1v;
            *reinterpret_cast<uint4*>(B2 + offs) = w2v;
        }
    };

    auto comp_chunk = [&](int buf) {
        const uint32_t sA1 = sb + SO_A1 + buf*16384;
        const uint32_t sB1 = sb + SO_B1 + buf*8192;
#pragma unroll
        for (int ks = 0; ks < 4; ++ks) {
            const int kb = ks*2;
            uint32_t a1f[2][4], a2f[2][4], b1f[2][4], b2f[2][4];
#pragma unroll
            for (int mt = 0; mt < 2; ++mt) {
                int row = wm*32 + mt*16 + (lane & 15);
                int col = (kb + (lane >> 4)) ^ (row & 7);
                uint32_t ad = sA1 + row*128 + col*16;
                ldsm4(a1f[mt], ad);
                ldsm4(a2f[mt], ad + (SO_A2 - SO_A1));
            }
#pragma unroll
            for (int ng = 0; ng < 2; ++ng) {
                int rowb = wn*32 + ng*16 + (lane & 7) + ((lane >> 4) << 3);
                int colb = (kb + ((lane >> 3) & 1)) ^ (rowb & 7);
                uint32_t bd = sB1 + rowb*128 + colb*16;
                ldsm4(b1f[ng], bd);
                ldsm4(b2f[ng], bd + (SO_B2 - SO_B1));
            }
#pragma unroll
            for (int mt = 0; mt < 2; ++mt)
#pragma unroll
                for (int ng = 0; ng < 2; ++ng)
#pragma unroll
                    for (int hf = 0; hf < 2; ++hf) {
                        float* c = acc[mt][ng*2 + hf];
                        uint32_t* ch = acch[mt][ng*2 + hf];
                        mma16816(c, a1f[mt], &b1f[ng][hf*2]);
                        mma16816h(ch, a1f[mt], &b2f[ng][hf*2]);
                        mma16816h(ch, a2f[mt], &b1f[ng][hf*2]);
                    }
        }
    };

    ldg_chunk(0);
    sts_chunk(0, 0);
#pragma unroll 1
    for (int ch = 0; ch < NCH; ++ch) {
        if (ch + 1 < NCH) ldg_chunk(ch + 1);
        __syncthreads();
        comp_chunk(ch & 1);
        if (ch + 1 < NCH) sts_chunk(ch + 1, (ch + 1) & 1);
    }
    __syncthreads();   // all comp done; safe to overlay ls

    // ---- dump accumulators (+ scaled corrections) to ls[128][68] ----
    float* ls = reinterpret_cast<float*>(smem + SO_LS);
#pragma unroll
    for (int mt = 0; mt < 2; ++mt)
#pragma unroll
        for (int nt = 0; nt < 4; ++nt) {
            int row = wm*32 + mt*16 + (lane >> 2);
            int col = wn*32 + nt*8 + (lane & 3)*2;
            __half2 hc0 = *reinterpret_cast<__half2*>(&acch[mt][nt][0]);
            __half2 hc1 = *reinterpret_cast<__half2*>(&acch[mt][nt][1]);
            float2 c01 = __half22float2(hc0);
            float2 c23 = __half22float2(hc1);
            *reinterpret_cast<float2*>(ls + row*68 + col) =
                make_float2(acc[mt][nt][0] + c01.x*CORR_SCALE,
                            acc[mt][nt][1] + c01.y*CORR_SCALE);
            *reinterpret_cast<float2*>(ls + (row + 8)*68 + col) =
                make_float2(acc[mt][nt][2] + c23.x*CORR_SCALE,
                            acc[mt][nt][3] + c23.y*CORR_SCALE);
        }
    __syncthreads();

    // ---- per-token epilogue (warps 0-3, 1 token per thread) ----
    float* bs = reinterpret_cast<float*>(smem + SO_BS);
    float* zred = reinterpret_cast<float*>(smem + SO_ZRED);
    float lg[64];
    float zl = 0.f;
    if (tid < 128) {
        const int t = tid;
#pragma unroll
        for (int e = 0; e < 64; ++e) lg[e] = ls[t*68 + e] + bs[e];

        float mx = lg[0];
#pragma unroll
        for (int e = 1; e < 64; ++e) mx = fmaxf(mx, lg[e]);
        float ssum = 0.f;
#pragma unroll
        for (int e = 0; e < 64; ++e) { float p = expf(lg[e] - mx); lg[e] = p; ssum += p; }
        float logz = mx + logf(ssum);
        float inv = 1.f / ssum;
#pragma unroll
        for (int e = 0; e < 64; ++e) lg[e] *= inv;

        float p0 = -1.f, p1 = -1.f; int i0 = 0, i1 = 0;
#pragma unroll
        for (int e = 0; e < 64; ++e) {
            float v = lg[e];
            if (v > p0) { p1 = p0; i1 = i0; p0 = v; i0 = e; }
            else if (v > p1) { p1 = v; i1 = e; }
        }
        const int token = tok0 + t;
        g_gate0[token] = p0; g_gate1[token] = p1;
        g_e0[token] = i0;    g_e1[token] = i1;
        const int grp = token >> 12;
        atomicAdd(&g_cnt[grp*E + i0], 1);
        atomicAdd(&g_cnt[grp*E + i1], 1);
        zl = logz * logz;
    }
    __syncthreads();

    if (tid < 128) {
        // probs back into ls
        float* row = ls + tid*68;
#pragma unroll
        for (int c = 0; c < 16; ++c)
            *reinterpret_cast<float4*>(row + c*4) =
                make_float4(lg[4*c], lg[4*c+1], lg[4*c+2], lg[4*c+3]);
#pragma unroll
        for (int o = 16; o; o >>= 1) zl += __shfl_xor_sync(0xffffffffu, zl, o);
        if (lane == 0) zred[wid] = zl;
    }
    __syncthreads();

    // coalesced prob copy-out + deterministic per-CTA per-expert sums
    // (expert id k&63 is invariant under stride 256)
    float* P = out + P_OFF + (size_t)tok0*64;
    float s = 0.f;
    for (int k = tid; k < TM*64; k += 256) {
        float v = ls[(k >> 6)*68 + (k & 63)];
        P[k] = v;
        s += v;
    }
    psums[tid >> 6][tid & 63] = s;
    __syncthreads();
    if (tid < 64)
        g_psum2[blockIdx.x*64 + tid] =
            psums[0][tid] + psums[1][tid] + psums[2][tid] + psums[3][tid];

    if (tid == 0)
        g_zpart[blockIdx.x] = zred[0] + zred[1] + zred[2] + zred[3];
}

// ---------------- K2: stable rank by gate0 (descending), float4-vectorized ----------------
__global__ __launch_bounds__(256) void k2_rank() {
    __shared__ __align__(16) float gs[T];
    const int tid = threadIdx.x;
    const int grp = blockIdx.y;
    for (int i = tid; i < T; i += 256) gs[i] = g_gate0[grp*T + i];
    __syncthreads();
    const int t = blockIdx.x * 256 + tid;
    const float gi = gs[t];
    int rank = 0;
    const float4* gv = reinterpret_cast<const float4*>(gs);
#pragma unroll 4
    for (int j = 0; j < T/4; ++j) {
        float4 v = gv[j];
        int j4 = j*4;
        rank += (v.x > gi) || (v.x == gi && (j4    ) < t);
        rank += (v.y > gi) || (v.y == gi && (j4 + 1) < t);
        rank += (v.z > gi) || (v.z == gi && (j4 + 2) < t);
        rank += (v.w > gi) || (v.w == gi && (j4 + 3) < t);
    }
    int e0 = g_e0[grp*T + t], e1 = g_e1[grp*T + t];
    g_sorted[grp*T + rank] = t | (e0 << 12) | (e1 << 18);
}

// ---------------- K3: expert buffer priorities + dispatch/combine ----------------
// 1024 threads; sequential packed load (no random gathers), 32 warp segments,
// warp-local running counts, exclusive scan over warp histograms, scatter.
__global__ __launch_bounds__(1024) void k3_prio(float* __restrict__ out, const int* __restrict__ capPtr) {
    __shared__ unsigned char se[2*T];
    __shared__ unsigned char soff[2*T];
    __shared__ short stok[T];
    __shared__ int wcnt[32][64];
    __shared__ int wbase[32][64];

    const int tid = threadIdx.x;
    const int grp = blockIdx.x;
    const int cap = capPtr ? *capPtr : 160;
    const int w = tid >> 5, lane = tid & 31;
    const unsigned lt = (1u << lane) - 1u;

    wcnt[w][lane] = 0;
    wcnt[w][lane + 32] = 0;

    // sequential packed load: one coalesced pass fills tok, e0, e1
    for (int p = tid; p < T; p += 1024) {
        int pk = g_sorted[grp*T + p];
        stok[p] = (short)(pk & 4095);
        se[p]     = (unsigned char)((pk >> 12) & 63);
        se[p + T] = (unsigned char)((pk >> 18) & 63);
    }
    __syncthreads();

    // warp-sequential running counts over 8 sub-chunks of each 256-segment
#pragma unroll
    for (int i = 0; i < 8; ++i) {
        int p = w*256 + i*32 + lane;
        int e = se[p];
        unsigned m = __match_any_sync(0xffffffffu, e);
        int lrank = __popc(m & lt);
        int off = wcnt[w][e] + lrank;
        soff[p] = (unsigned char)off;
        __syncwarp();
        if (lane == (__ffs(m) - 1)) wcnt[w][e] += __popc(m);
        __syncwarp();
    }
    __syncthreads();

    // exclusive scan over warps, per expert
    if (tid < 64) {
        int run = 0;
#pragma unroll
        for (int ww = 0; ww < 32; ++ww) {
            wbase[ww][tid] = run;
            run += wcnt[ww][tid];
        }
    }
    __syncthreads();

    // scatter priorities back to token order
#pragma unroll
    for (int i = 0; i < 8; ++i) {
        int p = i*1024 + tid;
        int prio = wbase[p >> 8][se[p]] + soff[p];
        int tok = stok[p & (T-1)];
        if (p < T) g_prio0[grp*T + tok] = prio; else g_prio1[grp*T + tok] = prio;
    }
    __syncthreads();

    // final per-token outputs for this group
    for (int t = tid; t < T; t += 1024) {
        int idx = grp*T + t;
        int e0 = g_e0[idx], e1 = g_e1[idx];
        int pr0 = g_prio0[idx], pr1 = g_prio1[idx];
        float gt0 = g_gate0[idx], gt1 = g_gate1[idx];
        float4 d = make_float4((float)e0, (float)pr0, (float)e1, (float)pr1);
        reinterpret_cast<float4*>(out + DI_OFF)[idx] = d;
        float2 cc = make_float2(pr0 < cap ? gt0 : 0.f, pr1 < cap ? gt1 : 0.f);
        reinterpret_cast<float2*>(out + CW_OFF)[idx] = cc;
    }
}

// ---------------- K5: final scalars (deterministic reduction of per-CTA sums) ----------------
__global__ __launch_bounds__(512) void k5_final(float* __restrict__ out) {
    __shared__ float red[16];
    const int tid = threadIdx.x;       // 512 = 8 groups x 64 experts
    const int g = tid >> 6, e = tid & 63;
    float ps = 0.f;
#pragma unroll
    for (int c = 0; c < 32; ++c) ps += g_psum2[(g*32 + c)*64 + e];
    float a = (float)g_cnt[g*E + e] * ps;
#pragma unroll
    for (int o = 16; o; o >>= 1) a += __shfl_xor_sync(0xffffffffu, a, o);
    if ((tid & 31) == 0) red[tid >> 5] = a;
    __syncthreads();
    if (tid == 0) {
        float s = 0.f;
#pragma unroll
        for (int i = 0; i < 16; ++i) s += red[i];
        float z = 0.f;
        for (int i = 0; i < NCTA; ++i) z += g_zpart[i];
        out[AUX_OFF] = s * (1.f / 2097152.f);
        out[Z_OFF]   = z * (1.f / 32768.f);
    }
}

extern "C" void kernel_launch(void* const* d_in, const int* in_sizes, int n_in,
                              void* d_out, int out_size) {
    const float* X = (const float*)d_in[0];
    const float* W = (const float*)d_in[1];
    const float* B = (const float*)d_in[2];
    const int* cap = (n_in > 3) ? (const int*)d_in[3] : nullptr;
    float* out = (float*)d_out;

    cudaFuncSetAttribute(k1_gemm, cudaFuncAttributeMaxDynamicSharedMemorySize, SMEM_TOTAL);

    k0_prep<<<128, 256>>>(W);
    k1_gemm<<<NCTA, 256, SMEM_TOTAL>>>(X, B, out);
    k2_rank<<<dim3(16, 8), 256>>>();
    k3_prio<<<G, 1024>>>(out, cap);
    k5_final<<<1, 512>>>(out);
}